// round 7
// baseline (speedup 1.0000x reference)
#include <cuda_runtime.h>
#include <cstdint>

#define N_TOK   2048
#define D_IN    2048
#define D_OUT   2048
#define NEXP    8
#define BM      128
#define BN      128
#define BK      32
#define ASTRIDE 36          // BK + 4 pad: conflict-free fragment reads, rows 16B-aligned
#define NTHREADS 256
#define MAX_MTILES 40
#define NKTILES (D_IN / BK)                 // 64
#define NSTAGE  3
#define STAGE_WORDS (BM * ASTRIDE)
#define SMEM_BYTES (NSTAGE * 2 * STAGE_WORDS * 4)   // 110592 B; 2 CTAs = 221KB <= 228KB

__global__ void zero_out_kernel(float4* __restrict__ out) {
    int i = blockIdx.x * blockDim.x + threadIdx.x;
    out[i] = make_float4(0.f, 0.f, 0.f, 0.f);
}

__device__ __forceinline__ uint32_t f2tf32(uint32_t fbits) {
    uint32_t u;
    asm("cvt.rna.tf32.f32 %0, %1;" : "=r"(u) : "r"(fbits));
    return u;
}

__device__ __forceinline__ void cpasync16(uint32_t saddr, const void* gaddr) {
    asm volatile("cp.async.cg.shared.global [%0], [%1], 16;" :: "r"(saddr), "l"(gaddr));
}

extern __shared__ uint32_t dynsmem[];
#define AS(s, r, c) dynsmem[(s) * (2 * STAGE_WORDS) + (r) * ASTRIDE + (c)]
#define BS(s, r, c) dynsmem[(s) * (2 * STAGE_WORDS) + STAGE_WORDS + (r) * ASTRIDE + (c)]

__global__ __launch_bounds__(NTHREADS, 2)
void moe_gemm_kernel(const float* __restrict__ inputs,
                     const float* __restrict__ weight,
                     const int*   __restrict__ ssi,
                     const int*   __restrict__ offs,
                     const float* __restrict__ gates,
                     float*       __restrict__ out)
{
    __shared__ int   toks[BM];
    __shared__ float gts[BM];

    // ---- on-device grouped-GEMM tile scheduler ----
    int y = blockIdx.y;
    int e = -1, t = 0, segStart = 0, segLen = 0, cum = 0;
    #pragma unroll
    for (int i = 0; i < NEXP; i++) {
        int s   = (i == 0) ? 0 : offs[i - 1];
        int en  = offs[i];
        int len = en - s;
        int nt  = (len + BM - 1) / BM;
        if (e < 0 && y < cum + nt) { e = i; t = y - cum; segStart = s; segLen = len; }
        cum += nt;
    }
    if (e < 0) return;

    int p0 = segStart + t * BM;
    int rowsValid = segLen - t * BM;
    if (rowsValid > BM) rowsValid = BM;

    int tid = threadIdx.x;
    if (tid < BM) {
        if (tid < rowsValid) {
            int j = ssi[p0 + tid];
            toks[tid] = j >> 1;
            gts[tid]  = gates[j];
        } else {
            toks[tid] = 0;
            gts[tid]  = 0.f;
        }
    }
    __syncthreads();

    const float* W = weight + (size_t)e * D_OUT * D_IN + (size_t)(blockIdx.x * BN) * D_IN;

    int lane = tid & 31, warp = tid >> 5;
    int warpM = warp >> 1;
    int warpN = warp & 1;
    int g  = lane >> 2;
    int t4 = lane & 3;
    // phase stagger: odd warps walk the K-chunk starting at the midpoint,
    // desynchronizing LSU-burst vs HMMA phases across warps.
    int kkOfs = (warp & 1) * 16;

    int lr = tid >> 3;   // 0..31 row base for async loads
    int lg = tid & 7;    // 16B group within a 32-float row

    const float* aptr[4];
    const float* bptr[4];
    #pragma unroll
    for (int i = 0; i < 4; i++) {
        int r = lr + i * 32;
        aptr[i] = inputs + (size_t)toks[r] * D_IN + lg * 4;
        bptr[i] = W + (size_t)r * D_IN + lg * 4;
    }

    float c[2][8][4];
    #pragma unroll
    for (int m = 0; m < 2; m++)
        #pragma unroll
        for (int n = 0; n < 8; n++)
            #pragma unroll
            for (int q = 0; q < 4; q++) c[m][n][q] = 0.f;

    // ---- prologue: stages 0 and 1 ----
    #pragma unroll
    for (int s = 0; s < 2; s++) {
        #pragma unroll
        for (int i = 0; i < 4; i++) {
            int r = lr + i * 32;
            cpasync16((uint32_t)__cvta_generic_to_shared(&AS(s, r, lg * 4)), aptr[i] + s * BK);
            cpasync16((uint32_t)__cvta_generic_to_shared(&BS(s, r, lg * 4)), bptr[i] + s * BK);
        }
        asm volatile("cp.async.commit_group;");
    }

    for (int kt = 0; kt < NKTILES; kt++) {
        int buf = kt % NSTAGE;
        if (kt < NKTILES - 1) asm volatile("cp.async.wait_group 1;");
        else                  asm volatile("cp.async.wait_group 0;");
        __syncthreads();
        // single barrier per tile: this barrier also orders last iteration's
        // compute against the overwrite below (stage (kt+2)%3 was last read
        // in iteration kt-1, which every warp finished before arriving here).
        if (kt + 2 < NKTILES) {
            int nbuf = (kt + 2) % NSTAGE;
            int koff = (kt + 2) * BK;
            #pragma unroll
            for (int i = 0; i < 4; i++) {
                int r = lr + i * 32;
                cpasync16((uint32_t)__cvta_generic_to_shared(&AS(nbuf, r, lg * 4)), aptr[i] + koff);
                cpasync16((uint32_t)__cvta_generic_to_shared(&BS(nbuf, r, lg * 4)), bptr[i] + koff);
            }
            asm volatile("cp.async.commit_group;");
        }

        #pragma unroll
        for (int kz = 0; kz < BK; kz += 8) {
            int kk = (kz + kkOfs) & (BK - 1);
            uint32_t a[2][4], b[8][2];
            #pragma unroll
            for (int m = 0; m < 2; m++) {
                int r0 = warpM * 32 + m * 16;
                // A: rna-rounded (keeps coherent truncation bias to B side only)
                a[m][0] = f2tf32(AS(buf, r0 + g,     kk + t4));
                a[m][1] = f2tf32(AS(buf, r0 + 8 + g, kk + t4));
                a[m][2] = f2tf32(AS(buf, r0 + g,     kk + t4 + 4));
                a[m][3] = f2tf32(AS(buf, r0 + 8 + g, kk + t4 + 4));
            }
            #pragma unroll
            for (int n = 0; n < 8; n++) {
                int cb = warpN * 64 + n * 8 + g;
                // B: raw fp32 bits, HW truncates to tf32
                b[n][0] = BS(buf, cb, kk + t4);
                b[n][1] = BS(buf, cb, kk + t4 + 4);
            }
            #pragma unroll
            for (int m = 0; m < 2; m++)
                #pragma unroll
                for (int n = 0; n < 8; n++) {
                    asm volatile(
                        "mma.sync.aligned.m16n8k8.row.col.f32.tf32.tf32.f32 "
                        "{%0,%1,%2,%3},{%4,%5,%6,%7},{%8,%9},{%0,%1,%2,%3};"
                        : "+f"(c[m][n][0]), "+f"(c[m][n][1]),
                          "+f"(c[m][n][2]), "+f"(c[m][n][3])
                        : "r"(a[m][0]), "r"(a[m][1]), "r"(a[m][2]), "r"(a[m][3]),
                          "r"(b[n][0]), "r"(b[n][1]));
                }
        }
        // no trailing barrier (see comment at top of loop)
    }

    // ---- fused gate-combine epilogue: out[token] += gate * acc ----
    int colBase = blockIdx.x * BN + warpN * 64;
    #pragma unroll
    for (int m = 0; m < 2; m++) {
        int r0 = warpM * 32 + m * 16 + g;
        int r1 = r0 + 8;
        #pragma unroll
        for (int n = 0; n < 8; n++) {
            int col = colBase + n * 8 + t4 * 2;
            if (r0 < rowsValid) {
                float w = gts[r0];
                float* o = out + (size_t)toks[r0] * D_OUT + col;
                atomicAdd(o,     w * c[m][n][0]);
                atomicAdd(o + 1, w * c[m][n][1]);
            }
            if (r1 < rowsValid) {
                float w = gts[r1];
                float* o = out + (size_t)toks[r1] * D_OUT + col;
                atomicAdd(o,     w * c[m][n][2]);
                atomicAdd(o + 1, w * c[m][n][3]);
            }
        }
    }
}

extern "C" void kernel_launch(void* const* d_in, const int* in_sizes, int n_in,
                              void* d_out, int out_size)
{
    const float* inputs = (const float*)d_in[0];
    const float* weight = (const float*)d_in[1];
    const int*   ssi    = (const int*)  d_in[n_in - 4];
    const int*   offs   = (const int*)  d_in[n_in - 2];
    const float* gates  = (const float*)d_in[n_in - 1];
    float* out = (float*)d_out;

    cudaFuncSetAttribute(moe_gemm_kernel,
                         cudaFuncAttributeMaxDynamicSharedMemorySize, SMEM_BYTES);

    zero_out_kernel<<<(N_TOK * D_OUT / 4) / 256, 256>>>((float4*)out);
    dim3 grid(D_OUT / BN, MAX_MTILES);
    moe_gemm_kernel<<<grid, NTHREADS, SMEM_BYTES>>>(inputs, weight, ssi, offs, gates, out);
}

// round 9
// speedup vs baseline: 1.0377x; 1.0377x over previous
#include <cuda_runtime.h>
#include <cstdint>

#define N_TOK   2048
#define D_IN    2048
#define D_OUT   2048
#define NEXP    8
#define BM      128
#define BN      128
#define BK      32
#define ASTRIDE 36          // BK + 4 pad: conflict-free fragment reads, rows 16B-aligned
#define NTHREADS 256
#define MAX_MTILES 40
#define NKTILES (D_IN / BK)                 // 64
#define NSTAGE  3
#define STAGE_WORDS (BM * ASTRIDE)
#define SMEM_BYTES (NSTAGE * 2 * STAGE_WORDS * 4)   // 110592 B; 2 CTAs = 221KB <= 228KB

__global__ void zero_out_kernel(float4* __restrict__ out) {
    int i = blockIdx.x * blockDim.x + threadIdx.x;
    out[i] = make_float4(0.f, 0.f, 0.f, 0.f);
}

__device__ __forceinline__ uint32_t f2tf32(uint32_t fbits) {
    uint32_t u;
    asm("cvt.rna.tf32.f32 %0, %1;" : "=r"(u) : "r"(fbits));
    return u;
}

__device__ __forceinline__ void cpasync16(uint32_t saddr, const void* gaddr) {
    asm volatile("cp.async.cg.shared.global [%0], [%1], 16;" :: "r"(saddr), "l"(gaddr));
}

__device__ __forceinline__ void mma_tf32(float* c4, const uint32_t* a4, const uint32_t* b2) {
    asm volatile(
        "mma.sync.aligned.m16n8k8.row.col.f32.tf32.tf32.f32 "
        "{%0,%1,%2,%3},{%4,%5,%6,%7},{%8,%9},{%0,%1,%2,%3};"
        : "+f"(c4[0]), "+f"(c4[1]), "+f"(c4[2]), "+f"(c4[3])
        : "r"(a4[0]), "r"(a4[1]), "r"(a4[2]), "r"(a4[3]),
          "r"(b2[0]), "r"(b2[1]));
}

extern __shared__ uint32_t dynsmem[];
#define AS(s, r, c) dynsmem[(s) * (2 * STAGE_WORDS) + (r) * ASTRIDE + (c)]
#define BS(s, r, c) dynsmem[(s) * (2 * STAGE_WORDS) + STAGE_WORDS + (r) * ASTRIDE + (c)]

__global__ __launch_bounds__(NTHREADS, 2)
void moe_gemm_kernel(const float* __restrict__ inputs,
                     const float* __restrict__ weight,
                     const int*   __restrict__ ssi,
                     const int*   __restrict__ offs,
                     const float* __restrict__ gates,
                     float*       __restrict__ out)
{
    __shared__ int   toks[BM];
    __shared__ float gts[BM];

    // ---- on-device grouped-GEMM tile scheduler ----
    int y = blockIdx.y;
    int e = -1, t = 0, segStart = 0, segLen = 0, cum = 0;
    #pragma unroll
    for (int i = 0; i < NEXP; i++) {
        int s   = (i == 0) ? 0 : offs[i - 1];
        int en  = offs[i];
        int len = en - s;
        int nt  = (len + BM - 1) / BM;
        if (e < 0 && y < cum + nt) { e = i; t = y - cum; segStart = s; segLen = len; }
        cum += nt;
    }
    if (e < 0) return;

    int p0 = segStart + t * BM;
    int rowsValid = segLen - t * BM;
    if (rowsValid > BM) rowsValid = BM;

    int tid = threadIdx.x;
    if (tid < BM) {
        if (tid < rowsValid) {
            int j = ssi[p0 + tid];
            toks[tid] = j >> 1;
            gts[tid]  = gates[j];
        } else {
            toks[tid] = 0;
            gts[tid]  = 0.f;
        }
    }
    __syncthreads();

    const float* W = weight + (size_t)e * D_OUT * D_IN + (size_t)(blockIdx.x * BN) * D_IN;

    int lane = tid & 31, warp = tid >> 5;
    int warpM = warp >> 1;
    int warpN = warp & 1;
    int g  = lane >> 2;
    int t4 = lane & 3;

    int lr = tid >> 3;   // 0..31 row base for async loads
    int lg = tid & 7;    // 16B group within a 32-float row

    const float* aptr[4];
    const float* bptr[4];
    #pragma unroll
    for (int i = 0; i < 4; i++) {
        int r = lr + i * 32;
        aptr[i] = inputs + (size_t)toks[r] * D_IN + lg * 4;
        bptr[i] = W + (size_t)r * D_IN + lg * 4;
    }

    float c[2][8][4];
    #pragma unroll
    for (int m = 0; m < 2; m++)
        #pragma unroll
        for (int n = 0; n < 8; n++)
            #pragma unroll
            for (int q = 0; q < 4; q++) c[m][n][q] = 0.f;

    // ---- prologue: stages 0 and 1 ----
    #pragma unroll
    for (int s = 0; s < 2; s++) {
        #pragma unroll
        for (int i = 0; i < 4; i++) {
            int r = lr + i * 32;
            cpasync16((uint32_t)__cvta_generic_to_shared(&AS(s, r, lg * 4)), aptr[i] + s * BK);
            cpasync16((uint32_t)__cvta_generic_to_shared(&BS(s, r, lg * 4)), bptr[i] + s * BK);
        }
        asm volatile("cp.async.commit_group;");
    }

    int ar0 = warpM * 32 + g;          // A fragment rows: ar0, ar0+8, +16, +24
    int bc0 = warpN * 64 + g;          // B fragment col base

    for (int kt = 0; kt < NKTILES; kt++) {
        int buf = kt % NSTAGE;
        if (kt < NKTILES - 1) asm volatile("cp.async.wait_group 1;");
        else                  asm volatile("cp.async.wait_group 0;");
        __syncthreads();
        // prefetch stage kt+2 (overlaps this tile's compute)
        if (kt + 2 < NKTILES) {
            int nbuf = (kt + 2) % NSTAGE;
            int koff = (kt + 2) * BK;
            #pragma unroll
            for (int i = 0; i < 4; i++) {
                int r = lr + i * 32;
                cpasync16((uint32_t)__cvta_generic_to_shared(&AS(nbuf, r, lg * 4)), aptr[i] + koff);
                cpasync16((uint32_t)__cvta_generic_to_shared(&BS(nbuf, r, lg * 4)), bptr[i] + koff);
            }
            asm volatile("cp.async.commit_group;");
        }

        // ---- intra-warp software-pipelined fragment/MMA loop ----
        uint32_t afr[2][2][4];   // [pipe][m][frag]
        uint32_t b0f[2][4][2];   // [pipe][n=0..3][frag]
        uint32_t b1f[4][2];      // [n=4..7][frag], single-buffered

        // preload step 0
        #pragma unroll
        for (int m = 0; m < 2; m++) {
            int r0 = ar0 + m * 16;
            afr[0][m][0] = f2tf32(AS(buf, r0,      t4));
            afr[0][m][1] = f2tf32(AS(buf, r0 + 8,  t4));
            afr[0][m][2] = f2tf32(AS(buf, r0,      t4 + 4));
            afr[0][m][3] = f2tf32(AS(buf, r0 + 8,  t4 + 4));
        }
        #pragma unroll
        for (int n = 0; n < 4; n++) {
            int cb = bc0 + n * 8;
            b0f[0][n][0] = BS(buf, cb, t4);
            b0f[0][n][1] = BS(buf, cb, t4 + 4);
        }

        #pragma unroll
        for (int kz = 0; kz < 4; kz++) {
            int cur = kz & 1, nxt = cur ^ 1;
            int kk = kz * 8;
            // load b half1 for this step
            #pragma unroll
            for (int n = 0; n < 4; n++) {
                int cb = bc0 + (n + 4) * 8;
                b1f[n][0] = BS(buf, cb, kk + t4);
                b1f[n][1] = BS(buf, cb, kk + t4 + 4);
            }
            // MMA half0 (n = 0..3)
            #pragma unroll
            for (int m = 0; m < 2; m++)
                #pragma unroll
                for (int n = 0; n < 4; n++)
                    mma_tf32(c[m][n], afr[cur][m], b0f[cur][n]);
            // prefetch next step's a and b-half0 (overlaps MMAs)
            if (kz < 3) {
                int kn = kk + 8;
                #pragma unroll
                for (int m = 0; m < 2; m++) {
                    int r0 = ar0 + m * 16;
                    afr[nxt][m][0] = f2tf32(AS(buf, r0,     kn + t4));
                    afr[nxt][m][1] = f2tf32(AS(buf, r0 + 8, kn + t4));
                    afr[nxt][m][2] = f2tf32(AS(buf, r0,     kn + t4 + 4));
                    afr[nxt][m][3] = f2tf32(AS(buf, r0 + 8, kn + t4 + 4));
                }
                #pragma unroll
                for (int n = 0; n < 4; n++) {
                    int cb = bc0 + n * 8;
                    b0f[nxt][n][0] = BS(buf, cb, kn + t4);
                    b0f[nxt][n][1] = BS(buf, cb, kn + t4 + 4);
                }
            }
            // MMA half1 (n = 4..7)
            #pragma unroll
            for (int m = 0; m < 2; m++)
                #pragma unroll
                for (int n = 0; n < 4; n++)
                    mma_tf32(c[m][n + 4], afr[cur][m], b1f[n]);
        }
        __syncthreads();
    }

    // ---- fused gate-combine epilogue: out[token] += gate * acc ----
    int colBase = blockIdx.x * BN + warpN * 64;
    #pragma unroll
    for (int m = 0; m < 2; m++) {
        int r0 = warpM * 32 + m * 16 + g;
        int r1 = r0 + 8;
        #pragma unroll
        for (int n = 0; n < 8; n++) {
            int col = colBase + n * 8 + t4 * 2;
            if (r0 < rowsValid) {
                float w = gts[r0];
                float* o = out + (size_t)toks[r0] * D_OUT + col;
                atomicAdd(o,     w * c[m][n][0]);
                atomicAdd(o + 1, w * c[m][n][1]);
            }
            if (r1 < rowsValid) {
                float w = gts[r1];
                float* o = out + (size_t)toks[r1] * D_OUT + col;
                atomicAdd(o,     w * c[m][n][2]);
                atomicAdd(o + 1, w * c[m][n][3]);
            }
        }
    }
}

extern "C" void kernel_launch(void* const* d_in, const int* in_sizes, int n_in,
                              void* d_out, int out_size)
{
    const float* inputs = (const float*)d_in[0];
    const float* weight = (const float*)d_in[1];
    const int*   ssi    = (const int*)  d_in[n_in - 4];
    const int*   offs   = (const int*)  d_in[n_in - 2];
    const float* gates  = (const float*)d_in[n_in - 1];
    float* out = (float*)d_out;

    cudaFuncSetAttribute(moe_gemm_kernel,
                         cudaFuncAttributeMaxDynamicSharedMemorySize, SMEM_BYTES);

    zero_out_kernel<<<(N_TOK * D_OUT / 4) / 256, 256>>>((float4*)out);
    dim3 grid(D_OUT / BN, MAX_MTILES);
    moe_gemm_kernel<<<grid, NTHREADS, SMEM_BYTES>>>(inputs, weight, ssi, offs, gates, out);
}

// round 11
// speedup vs baseline: 1.0611x; 1.0226x over previous
#include <cuda_runtime.h>
#include <cstdint>

#define N_TOK   2048
#define D_IN    2048
#define D_OUT   2048
#define NEXP    8
#define TOPK    2
#define BM      128
#define BN      128
#define BK      32
#define ASTRIDE 36
#define NTHREADS 256
#define MAX_MTILES 40
#define NKTILES (D_IN / BK)
#define NSTAGE  3
#define STAGE_WORDS (BM * ASTRIDE)
#define SMEM_BYTES (NSTAGE * 2 * STAGE_WORDS * 4)   // 110592 B; 2 CTAs/SM

// per-(token,slot) GEMM results, combined by the gate kernel afterwards
__device__ float g_yflat[(size_t)N_TOK * TOPK * D_OUT];   // 33.5 MB static scratch

__device__ __forceinline__ uint32_t f2tf32(uint32_t fbits) {
    uint32_t u;
    asm("cvt.rna.tf32.f32 %0, %1;" : "=r"(u) : "r"(fbits));
    return u;
}

__device__ __forceinline__ void cpasync16(uint32_t saddr, const void* gaddr) {
    asm volatile("cp.async.cg.shared.global [%0], [%1], 16;" :: "r"(saddr), "l"(gaddr));
}

__device__ __forceinline__ void mma_tf32(float* c4, const uint32_t* a4, const uint32_t* b2) {
    asm volatile(
        "mma.sync.aligned.m16n8k8.row.col.f32.tf32.tf32.f32 "
        "{%0,%1,%2,%3},{%4,%5,%6,%7},{%8,%9},{%0,%1,%2,%3};"
        : "+f"(c4[0]), "+f"(c4[1]), "+f"(c4[2]), "+f"(c4[3])
        : "r"(a4[0]), "r"(a4[1]), "r"(a4[2]), "r"(a4[3]),
          "r"(b2[0]), "r"(b2[1]));
}

extern __shared__ uint32_t dynsmem[];
#define AS(s, r, c) dynsmem[(s) * (2 * STAGE_WORDS) + (r) * ASTRIDE + (c)]
#define BS(s, r, c) dynsmem[(s) * (2 * STAGE_WORDS) + STAGE_WORDS + (r) * ASTRIDE + (c)]

__global__ __launch_bounds__(NTHREADS, 2)
void moe_gemm_kernel(const float* __restrict__ inputs,
                     const float* __restrict__ weight,
                     const int*   __restrict__ ssi,
                     const int*   __restrict__ offs)
{
    __shared__ int jidx[BM];   // flat (token,slot) index per tile row

    // ---- on-device grouped-GEMM tile scheduler ----
    int y = blockIdx.y;
    int e = -1, t = 0, segStart = 0, segLen = 0, cum = 0;
    #pragma unroll
    for (int i = 0; i < NEXP; i++) {
        int s   = (i == 0) ? 0 : offs[i - 1];
        int en  = offs[i];
        int len = en - s;
        int nt  = (len + BM - 1) / BM;
        if (e < 0 && y < cum + nt) { e = i; t = y - cum; segStart = s; segLen = len; }
        cum += nt;
    }
    if (e < 0) return;

    int p0 = segStart + t * BM;
    int rowsValid = segLen - t * BM;
    if (rowsValid > BM) rowsValid = BM;

    int tid = threadIdx.x;
    if (tid < BM)
        jidx[tid] = (tid < rowsValid) ? ssi[p0 + tid] : 0;
    __syncthreads();

    const float* W = weight + (size_t)e * D_OUT * D_IN + (size_t)(blockIdx.x * BN) * D_IN;

    int lane = tid & 31, warp = tid >> 5;
    int warpM = warp >> 1;
    int warpN = warp & 1;
    int g  = lane >> 2;
    int t4 = lane & 3;

    int lr = tid >> 3;
    int lg = tid & 7;

    const float* aptr[4];
    const float* bptr[4];
    #pragma unroll
    for (int i = 0; i < 4; i++) {
        int r = lr + i * 32;
        aptr[i] = inputs + (size_t)(jidx[r] >> 1) * D_IN + lg * 4;
        bptr[i] = W + (size_t)r * D_IN + lg * 4;
    }

    float c[2][8][4];
    #pragma unroll
    for (int m = 0; m < 2; m++)
        #pragma unroll
        for (int n = 0; n < 8; n++)
            #pragma unroll
            for (int q = 0; q < 4; q++) c[m][n][q] = 0.f;

    // ---- prologue: stages 0 and 1 ----
    #pragma unroll
    for (int s = 0; s < 2; s++) {
        #pragma unroll
        for (int i = 0; i < 4; i++) {
            int r = lr + i * 32;
            cpasync16((uint32_t)__cvta_generic_to_shared(&AS(s, r, lg * 4)), aptr[i] + s * BK);
            cpasync16((uint32_t)__cvta_generic_to_shared(&BS(s, r, lg * 4)), bptr[i] + s * BK);
        }
        asm volatile("cp.async.commit_group;");
    }

    for (int kt = 0; kt < NKTILES; kt++) {
        int buf = kt % NSTAGE;
        if (kt < NKTILES - 1) asm volatile("cp.async.wait_group 1;");
        else                  asm volatile("cp.async.wait_group 0;");
        __syncthreads();
        if (kt + 2 < NKTILES) {
            int nbuf = (kt + 2) % NSTAGE;
            int koff = (kt + 2) * BK;
            #pragma unroll
            for (int i = 0; i < 4; i++) {
                int r = lr + i * 32;
                cpasync16((uint32_t)__cvta_generic_to_shared(&AS(nbuf, r, lg * 4)), aptr[i] + koff);
                cpasync16((uint32_t)__cvta_generic_to_shared(&BS(nbuf, r, lg * 4)), bptr[i] + koff);
            }
            asm volatile("cp.async.commit_group;");
        }

        #pragma unroll
        for (int kk = 0; kk < BK; kk += 8) {
            uint32_t a[2][4], b[8][2];
            #pragma unroll
            for (int m = 0; m < 2; m++) {
                int r0 = warpM * 32 + m * 16;
                a[m][0] = f2tf32(AS(buf, r0 + g,     kk + t4));
                a[m][1] = f2tf32(AS(buf, r0 + 8 + g, kk + t4));
                a[m][2] = f2tf32(AS(buf, r0 + g,     kk + t4 + 4));
                a[m][3] = f2tf32(AS(buf, r0 + 8 + g, kk + t4 + 4));
            }
            #pragma unroll
            for (int n = 0; n < 8; n++) {
                int cb = warpN * 64 + n * 8 + g;
                b[n][0] = BS(buf, cb, kk + t4);
                b[n][1] = BS(buf, cb, kk + t4 + 4);
            }
            #pragma unroll
            for (int m = 0; m < 2; m++)
                #pragma unroll
                for (int n = 0; n < 8; n++)
                    mma_tf32(c[m][n], a[m], b[n]);
        }
        __syncthreads();
    }

    // ---- epilogue: plain vectorized stores to scratch (no atomics, no gating) ----
    int colBase = blockIdx.x * BN + warpN * 64;
    #pragma unroll
    for (int m = 0; m < 2; m++) {
        int r0 = warpM * 32 + m * 16 + g;
        int r1 = r0 + 8;
        float* o0 = g_yflat + (size_t)jidx[r0] * D_OUT + colBase;
        float* o1 = g_yflat + (size_t)jidx[r1] * D_OUT + colBase;
        bool v0 = (r0 < rowsValid), v1 = (r1 < rowsValid);
        #pragma unroll
        for (int n = 0; n < 8; n++) {
            int col = n * 8 + t4 * 2;
            if (v0) *reinterpret_cast<float2*>(o0 + col) = make_float2(c[m][n][0], c[m][n][1]);
            if (v1) *reinterpret_cast<float2*>(o1 + col) = make_float2(c[m][n][2], c[m][n][3]);
        }
    }
}

// out[t,:] = gates[2t] * y[2t,:] + gates[2t+1] * y[2t+1,:]
__global__ __launch_bounds__(256)
void combine_kernel(const float* __restrict__ gates, float* __restrict__ out) {
    int i = blockIdx.x * blockDim.x + threadIdx.x;   // float4 index over [N_TOK, D_OUT/4]
    int tok  = i >> (11 - 2);                        // D_OUT/4 = 512 per token
    int cq   = i & 511;
    float g0 = gates[tok * 2];
    float g1 = gates[tok * 2 + 1];
    const float4* y0 = reinterpret_cast<const float4*>(g_yflat + (size_t)(tok * 2)     * D_OUT) + cq;
    const float4* y1 = reinterpret_cast<const float4*>(g_yflat + (size_t)(tok * 2 + 1) * D_OUT) + cq;
    float4 a = *y0, b = *y1;
    float4 r;
    r.x = g0 * a.x + g1 * b.x;
    r.y = g0 * a.y + g1 * b.y;
    r.z = g0 * a.z + g1 * b.z;
    r.w = g0 * a.w + g1 * b.w;
    reinterpret_cast<float4*>(out)[i] = r;
}

extern "C" void kernel_launch(void* const* d_in, const int* in_sizes, int n_in,
                              void* d_out, int out_size)
{
    const float* inputs = (const float*)d_in[0];
    const float* weight = (const float*)d_in[1];
    const int*   ssi    = (const int*)  d_in[n_in - 4];
    const int*   offs   = (const int*)  d_in[n_in - 2];
    const float* gates  = (const float*)d_in[n_in - 1];
    float* out = (float*)d_out;

    cudaFuncSetAttribute(moe_gemm_kernel,
                         cudaFuncAttributeMaxDynamicSharedMemorySize, SMEM_BYTES);

    dim3 grid(D_OUT / BN, MAX_MTILES);
    moe_gemm_kernel<<<grid, NTHREADS, SMEM_BYTES>>>(inputs, weight, ssi, offs);
    combine_kernel<<<(N_TOK * D_OUT / 4) / 256, 256>>>(gates, out);
}